// round 16
// baseline (speedup 1.0000x reference)
#include <cuda_runtime.h>
#include <cuda_bf16.h>
#include <math.h>

#define NN 50000
#define NE 800000
#define NET 850000   // edges + self loops
#define D1 128
#define H1N 4
#define D2 64
#define NEG 0.2f
#define EPS 1e-5f
#define NBLK ((NN + 255) / 256)

// ---------------- scratch (static device globals; no allocation) ----------------
__device__ __align__(16) int      g_src[NE];
__device__ __align__(16) int      g_dst[NE];
__device__ __align__(16) int      g_rowptr[NN + 1];
__device__ __align__(16) int      g_cursor[NN];       // edge-degree, then scatter cursor
__device__ __align__(16) int      g_bsum[256];        // block sums for scan
__device__ __align__(16) int      g_csr_src[NET];     // src ids grouped by dst
__device__ __align__(16) float    g_h1[NN * D1];      // x @ W1 (fp32)
__device__ __align__(16) float    g_as1[NN * H1N];
__device__ __align__(16) float    g_ad1[NN * H1N];
__device__ __align__(16) float    g_hln[NN * D1];     // after LN+ReLU
__device__ __align__(16) float    g_t2[NN * D2];      // hln @ W2 (fp32)
__device__ __align__(16) float    g_as2[NN];
__device__ __align__(16) float    g_ad2[NN];
__device__ int g_is32;   // 1 => edge_index buffer is int32, 0 => int64
// g_is32 is NOT reset between calls: for fixed input it converges to the same
// value on every call, so work is identical call-to-call.

// ---------------- helpers ----------------
__device__ __forceinline__ float lrelu(float v) { return v > 0.f ? v : NEG * v; }

// ---------------- detect dtype + zero per-call cursor ----------------
__global__ void k_detect(const unsigned long long* __restrict__ p) {
    int i = blockIdx.x * blockDim.x + threadIdx.x;
    int st = gridDim.x * blockDim.x;
    for (int t = i; t < NN; t += st) g_cursor[t] = 0;
    int local = 0;
    for (int e = i; e < NE; e += st) {
        if ((p[e] >> 32) != 0ull) { local = 1; break; }
    }
    if (local) atomicExch(&g_is32, 1);
}

// ---------------- init: index convert + edge-degree histogram ----------------
__global__ void k_init(const void* __restrict__ eiv) {
    int i = blockIdx.x * blockDim.x + threadIdx.x;
    int st = gridDim.x * blockDim.x;
    int is32 = g_is32;
    if (is32) {
        const int* p = (const int*)eiv;
        for (int e = i; e < NE; e += st) {
            int s = p[e];
            int d = p[NE + e];
            g_src[e] = s;
            g_dst[e] = d;
            atomicAdd(&g_cursor[d], 1);
        }
    } else {
        const long long* p = (const long long*)eiv;
        for (int e = i; e < NE; e += st) {
            int s = (int)p[e];
            int d = (int)p[NE + e];
            g_src[e] = s;
            g_dst[e] = d;
            atomicAdd(&g_cursor[d], 1);
        }
    }
}

// ---------------- parallel scan (3 kernels); degree(n) = cursor[n] + 1 ----------------
__global__ void k_scan1() {
    __shared__ int sh[256];
    int t = threadIdx.x;
    int idx = blockIdx.x * 256 + t;
    sh[t] = (idx < NN) ? (g_cursor[idx] + 1) : 0;
    __syncthreads();
    for (int o = 128; o >= 1; o >>= 1) {
        if (t < o) sh[t] += sh[t + o];
        __syncthreads();
    }
    if (t == 0) g_bsum[blockIdx.x] = sh[0];
}

__global__ void k_scan2() {
    __shared__ int sh[256];
    int t = threadIdx.x;
    int v = (t < NBLK) ? g_bsum[t] : 0;
    sh[t] = v;
    __syncthreads();
    for (int o = 1; o < 256; o <<= 1) {
        int u = (t >= o) ? sh[t - o] : 0;
        __syncthreads();
        sh[t] += u;
        __syncthreads();
    }
    if (t < NBLK) g_bsum[t] = sh[t] - v;   // exclusive
    if (t == 0) g_rowptr[NN] = NET;
}

__global__ void k_scan3() {
    __shared__ int sh[256];
    int t = threadIdx.x;
    int idx = blockIdx.x * 256 + t;
    int v = (idx < NN) ? (g_cursor[idx] + 1) : 0;
    sh[t] = v;
    __syncthreads();
    for (int o = 1; o < 256; o <<= 1) {
        int u = (t >= o) ? sh[t - o] : 0;
        __syncthreads();
        sh[t] += u;
        __syncthreads();
    }
    if (idx < NN) {
        int run = g_bsum[blockIdx.x] + sh[t] - v;
        g_rowptr[idx] = run;
        g_csr_src[run] = idx;        // self loop first
        g_cursor[idx] = run + 1;
    }
}

__global__ void k_scatter() {
    int e = blockIdx.x * blockDim.x + threadIdx.x;
    if (e >= NE) return;
    int d = g_dst[e];
    int pos = atomicAdd(&g_cursor[d], 1);
    g_csr_src[pos] = g_src[e];
}

// ---------------- SGEMM (fp32 out) with fused attention-feature epilogue ----------------
template <int BM, int BN, int BK, int TM, int TN>
__global__ void sgemm_f32(const float* __restrict__ A, const float* __restrict__ B,
                          float* __restrict__ C, int M, int N, int K,
                          const float* __restrict__ att_s, const float* __restrict__ att_d,
                          float* __restrict__ as_out, float* __restrict__ ad_out,
                          int hc, int nh) {
    __shared__ float As[BK][BM];
    __shared__ float Bs[BK][BN];
    const int NTH = (BM / TM) * (BN / TN);
    int tid = threadIdx.x;
    int tx = tid % (BN / TN);
    int ty = tid / (BN / TN);
    int bm = blockIdx.x * BM;
    int bn = blockIdx.y * BN;

    float acc[TM][TN];
#pragma unroll
    for (int m = 0; m < TM; m++)
#pragma unroll
        for (int n = 0; n < TN; n++) acc[m][n] = 0.f;

    for (int k0 = 0; k0 < K; k0 += BK) {
#pragma unroll
        for (int i = tid; i < BM * BK / 4; i += NTH) {
            int row = i / (BK / 4);
            int c4 = i % (BK / 4);
            float4 v = make_float4(0.f, 0.f, 0.f, 0.f);
            int gr = bm + row;
            if (gr < M) v = *(const float4*)&A[(size_t)gr * K + k0 + c4 * 4];
            As[c4 * 4 + 0][row] = v.x;
            As[c4 * 4 + 1][row] = v.y;
            As[c4 * 4 + 2][row] = v.z;
            As[c4 * 4 + 3][row] = v.w;
        }
#pragma unroll
        for (int i = tid; i < BK * BN / 4; i += NTH) {
            int r = i / (BN / 4);
            int c4 = i % (BN / 4);
            *(float4*)&Bs[r][c4 * 4] = *(const float4*)&B[(size_t)(k0 + r) * N + bn + c4 * 4];
        }
        __syncthreads();
#pragma unroll
        for (int kk = 0; kk < BK; kk++) {
            float ra[TM], rb[TN];
#pragma unroll
            for (int m = 0; m < TM; m++) ra[m] = As[kk][ty * TM + m];
#pragma unroll
            for (int n = 0; n < TN; n++) rb[n] = Bs[kk][tx * TN + n];
#pragma unroll
            for (int m = 0; m < TM; m++)
#pragma unroll
                for (int n = 0; n < TN; n++) acc[m][n] += ra[m] * rb[n];
        }
        __syncthreads();
    }
#pragma unroll
    for (int m = 0; m < TM; m++) {
        int gr = bm + ty * TM + m;
        if (gr < M) {
            float4 v = make_float4(acc[m][0], acc[m][1], acc[m][2], acc[m][3]);
            *(float4*)&C[(size_t)gr * N + bn + tx * TN] = v;
        }
    }
    {
        int lph = hc / TN;                   // lanes per head: 8 (layer1) / 16 (layer2)
        int head = (bn + tx * TN) / hc;
        float avs[TN], avd[TN];
#pragma unroll
        for (int n = 0; n < TN; n++) {
            int col = bn + tx * TN + n;
            avs[n] = att_s[col];
            avd[n] = att_d[col];
        }
#pragma unroll
        for (int m = 0; m < TM; m++) {
            float ps = 0.f, pd = 0.f;
#pragma unroll
            for (int n = 0; n < TN; n++) {
                ps += acc[m][n] * avs[n];
                pd += acc[m][n] * avd[n];
            }
            for (int o = lph >> 1; o >= 1; o >>= 1) {
                ps += __shfl_down_sync(0xffffffffu, ps, o, lph);
                pd += __shfl_down_sync(0xffffffffu, pd, o, lph);
            }
            int gr = bm + ty * TM + m;
            if ((tx & (lph - 1)) == 0 && gr < M) {
                as_out[gr * nh + head] = ps;
                ad_out[gr * nh + head] = pd;
            }
        }
    }
}

// ---------------- layer1 aggregate: warp/node CSR gather, batched loads (MLP=8) ----------------
__global__ void k_agg1(const float* __restrict__ b1, const float* __restrict__ g1,
                       const float* __restrict__ be1) {
    int node = (blockIdx.x * blockDim.x + threadIdx.x) >> 5;
    int lane = threadIdx.x & 31;
    if (node >= NN) return;
    int start = g_rowptr[node];
    int end = g_rowptr[node + 1];
    int h = lane >> 3;
    int ln8 = lane & 7;
    float advh = g_ad1[node * H1N + h];

    float den = 0.f;
    float4 acc = make_float4(0.f, 0.f, 0.f, 0.f);
    int exsrc = (h << 3);

    int j0 = start + ln8;
    int s_pf = 0; float as_pf = 0.f;
    if (j0 < end) { s_pf = g_csr_src[j0]; as_pf = g_as1[s_pf * H1N + h]; }

    for (int c = start; c < end; c += 8) {
        int s_own = s_pf;
        float ex_own = __expf(lrelu(as_pf + advh));
        int jn = c + 8 + ln8;
        if (jn < end) { s_pf = g_csr_src[jn]; as_pf = g_as1[s_pf * H1N + h]; }
        int cnt = end - c;
        if (cnt >= 8) {
            // phase 1: all shfls
            int sv[8]; float exv[8];
#pragma unroll
            for (int j2 = 0; j2 < 8; j2++) {
                sv[j2] = __shfl_sync(0xffffffffu, s_own, j2);
                exv[j2] = __shfl_sync(0xffffffffu, ex_own, exsrc + j2);
            }
            // phase 2: all gathers (8 independent LDG.128 in flight)
            float4 hv[8];
#pragma unroll
            for (int j2 = 0; j2 < 8; j2++)
                hv[j2] = *(const float4*)&g_h1[(size_t)sv[j2] * D1 + lane * 4];
            // phase 3: accumulate
#pragma unroll
            for (int j2 = 0; j2 < 8; j2++) {
                den += exv[j2];
                acc.x += exv[j2] * hv[j2].x;
                acc.y += exv[j2] * hv[j2].y;
                acc.z += exv[j2] * hv[j2].z;
                acc.w += exv[j2] * hv[j2].w;
            }
        } else {
            for (int j2 = 0; j2 < cnt; j2++) {
                int s = __shfl_sync(0xffffffffu, s_own, j2);
                float ex = __shfl_sync(0xffffffffu, ex_own, exsrc + j2);
                float4 hv = *(const float4*)&g_h1[(size_t)s * D1 + lane * 4];
                den += ex;
                acc.x += ex * hv.x;
                acc.y += ex * hv.y;
                acc.z += ex * hv.z;
                acc.w += ex * hv.w;
            }
        }
    }

    float inv = 1.f / den;
    float4 bb = *(const float4*)&b1[lane * 4];
    float v0 = acc.x * inv + bb.x, v1 = acc.y * inv + bb.y;
    float v2 = acc.z * inv + bb.z, v3 = acc.w * inv + bb.w;
    float sum = v0 + v1 + v2 + v3;
    float sq = v0 * v0 + v1 * v1 + v2 * v2 + v3 * v3;
#pragma unroll
    for (int o = 16; o >= 1; o >>= 1) {
        sum += __shfl_xor_sync(0xffffffffu, sum, o);
        sq  += __shfl_xor_sync(0xffffffffu, sq, o);
    }
    float mu = sum * (1.f / D1);
    float var = sq * (1.f / D1) - mu * mu;
    float rs = rsqrtf(var + EPS);
    float4 gg = *(const float4*)&g1[lane * 4];
    float4 bt = *(const float4*)&be1[lane * 4];
    float4 outv;
    outv.x = fmaxf((v0 - mu) * rs * gg.x + bt.x, 0.f);
    outv.y = fmaxf((v1 - mu) * rs * gg.y + bt.y, 0.f);
    outv.z = fmaxf((v2 - mu) * rs * gg.z + bt.z, 0.f);
    outv.w = fmaxf((v3 - mu) * rs * gg.w + bt.w, 0.f);
    *(float4*)&g_hln[(size_t)node * D1 + lane * 4] = outv;
}

// ---------------- layer2 aggregate: warp/node CSR gather, batched loads (MLP=8) ----------------
__global__ void k_agg2(const float* __restrict__ b2, const float* __restrict__ g2,
                       const float* __restrict__ be2, float* __restrict__ out) {
    int node = (blockIdx.x * blockDim.x + threadIdx.x) >> 5;
    int lane = threadIdx.x & 31;
    if (node >= NN) return;
    int start = g_rowptr[node];
    int end = g_rowptr[node + 1];
    float ad = g_ad2[node];

    float den = 0.f;
    float2 acc = make_float2(0.f, 0.f);

    int j0 = start + lane;
    int s_pf = 0; float as_pf = 0.f;
    if (j0 < end) { s_pf = g_csr_src[j0]; as_pf = g_as2[s_pf]; }

    for (int c = start; c < end; c += 32) {
        int s_own = s_pf;
        float ex_own = __expf(lrelu(as_pf + ad));
        int jn = c + 32 + lane;
        if (jn < end) { s_pf = g_csr_src[jn]; as_pf = g_as2[s_pf]; }
        int cnt = end - c;
        if (cnt > 32) cnt = 32;
        int nb = cnt >> 3;           // full 8-batches
        for (int b = 0; b < nb; b++) {
            int base = b << 3;
            int sv[8]; float exv[8];
#pragma unroll
            for (int k = 0; k < 8; k++) {
                sv[k] = __shfl_sync(0xffffffffu, s_own, base + k);
                exv[k] = __shfl_sync(0xffffffffu, ex_own, base + k);
            }
            float2 hv[8];
#pragma unroll
            for (int k = 0; k < 8; k++)
                hv[k] = *(const float2*)&g_t2[(size_t)sv[k] * D2 + lane * 2];
#pragma unroll
            for (int k = 0; k < 8; k++) {
                den += exv[k];
                acc.x += exv[k] * hv[k].x;
                acc.y += exv[k] * hv[k].y;
            }
        }
        for (int j2 = nb << 3; j2 < cnt; j2++) {
            int s = __shfl_sync(0xffffffffu, s_own, j2);
            float ex = __shfl_sync(0xffffffffu, ex_own, j2);
            float2 hv = *(const float2*)&g_t2[(size_t)s * D2 + lane * 2];
            den += ex;
            acc.x += ex * hv.x;
            acc.y += ex * hv.y;
        }
    }

    float inv = 1.f / den;
    float2 bb = *(const float2*)&b2[lane * 2];
    float v0 = acc.x * inv + bb.x, v1 = acc.y * inv + bb.y;
    float sum = v0 + v1;
    float sq = v0 * v0 + v1 * v1;
#pragma unroll
    for (int o = 16; o >= 1; o >>= 1) {
        sum += __shfl_xor_sync(0xffffffffu, sum, o);
        sq  += __shfl_xor_sync(0xffffffffu, sq, o);
    }
    float mu = sum * (1.f / D2);
    float var = sq * (1.f / D2) - mu * mu;
    float rs = rsqrtf(var + EPS);
    float2 gg = *(const float2*)&g2[lane * 2];
    float2 bt = *(const float2*)&be2[lane * 2];
    float2 o2;
    o2.x = (v0 - mu) * rs * gg.x + bt.x;
    o2.y = (v1 - mu) * rs * gg.y + bt.y;
    *(float2*)&out[(size_t)node * D2 + lane * 2] = o2;
}

// ---------------- launcher ----------------
extern "C" void kernel_launch(void* const* d_in, const int* in_sizes, int n_in,
                              void* d_out, int out_size) {
    const float* x = 0; const void* ei = 0;
    const float* W1 = 0; const float* W2 = 0;
    const float* f128[5] = {0,0,0,0,0}; int n128 = 0;
    const float* f64[5]  = {0,0,0,0,0}; int n64 = 0;
    for (int i = 0; i < n_in; i++) {
        int sz = in_sizes[i];
        if (sz == NN * D1)            x  = (const float*)d_in[i];
        else if (sz == 2 * NE)        ei = d_in[i];
        else if (sz == D1 * D1)       W1 = (const float*)d_in[i];
        else if (sz == D1 * D2)       W2 = (const float*)d_in[i];
        else if (sz == 128 && n128 < 5) f128[n128++] = (const float*)d_in[i];
        else if (sz == 64  && n64  < 5) f64[n64++]   = (const float*)d_in[i];
    }
    const float* att_src1 = f128[0];
    const float* att_dst1 = f128[1];
    const float* b1       = f128[2];
    const float* gamma1   = f128[3];
    const float* beta1    = f128[4];
    const float* att_src2 = f64[0];
    const float* att_dst2 = f64[1];
    const float* b2       = f64[2];
    const float* gamma2   = f64[3];
    const float* beta2    = f64[4];
    float* out = (float*)d_out;
    (void)out_size;

    // real device addresses for symbols passed as kernel args
    float *p_h1 = 0, *p_hln = 0, *p_t2 = 0, *p_as1 = 0, *p_ad1 = 0, *p_as2 = 0, *p_ad2 = 0;
    cudaGetSymbolAddress((void**)&p_h1, g_h1);
    cudaGetSymbolAddress((void**)&p_hln, g_hln);
    cudaGetSymbolAddress((void**)&p_t2, g_t2);
    cudaGetSymbolAddress((void**)&p_as1, g_as1);
    cudaGetSymbolAddress((void**)&p_ad1, g_ad1);
    cudaGetSymbolAddress((void**)&p_as2, g_as2);
    cudaGetSymbolAddress((void**)&p_ad2, g_ad2);

    // fork: SGEMM1 (depends only on x/W1) runs concurrently with the CSR build.
    cudaStream_t s2;
    cudaStreamCreate(&s2);
    cudaEvent_t ev0, ev1;
    cudaEventCreateWithFlags(&ev0, cudaEventDisableTiming);
    cudaEventCreateWithFlags(&ev1, cudaEventDisableTiming);

    cudaEventRecord(ev0, 0);
    cudaStreamWaitEvent(s2, ev0, 0);
    {
        dim3 grid((NN + 127) / 128, D1 / 64);
        sgemm_f32<128, 64, 16, 8, 4><<<grid, 256, 0, s2>>>(x, W1, p_h1, NN, D1, D1,
                                                           att_src1, att_dst1, p_as1, p_ad1,
                                                           32, H1N);
    }
    cudaEventRecord(ev1, s2);

    // CSR build on the main stream (overlapped with SGEMM1)
    k_detect<<<256, 256>>>((const unsigned long long*)ei);
    k_init<<<2048, 256>>>(ei);
    k_scan1<<<NBLK, 256>>>();
    k_scan2<<<1, 256>>>();
    k_scan3<<<NBLK, 256>>>();
    k_scatter<<<(NE + 255) / 256, 256>>>();

    // join: agg1 needs both CSR and SGEMM1 results
    cudaStreamWaitEvent(0, ev1, 0);
    k_agg1<<<(NN * 32 + 255) / 256, 256>>>(b1, gamma1, beta1);

    // t2 = hln @ W2 (+ as2/ad2 in epilogue)
    {
        dim3 grid((NN + 127) / 128, D2 / 64);
        sgemm_f32<128, 64, 16, 8, 4><<<grid, 256>>>(p_hln, W2, p_t2, NN, D2, D1,
                                                    att_src2, att_dst2, p_as2, p_ad2,
                                                    64, 1);
    }
    k_agg2<<<(NN * 32 + 255) / 256, 256>>>(b2, gamma2, beta2, out);
}